// round 14
// baseline (speedup 1.0000x reference)
#include <cuda_runtime.h>
#include <math.h>
#include <stdint.h>

// ---------------- problem constants ----------------
#define NLVL   12
#define TBL    (1u << 19)
#define TMASK  (TBL - 1u)
#define EMBD   24
#define DOUT   257
#define TPB    256            // warps 0-3 producers, 4-7 consumers
#define TILE_P 256
#define STAGES 2

#define PRIME_Y 2654435761u
#define PRIME_Z 805459861u

struct Params { int res[NLVL]; };

// ---------------- f32x2 packed helpers (sm_103a) ----------------
__device__ __forceinline__ unsigned long long pack2_f32(float lo, float hi) {
    unsigned long long r;
    asm("mov.b64 %0, {%1, %2};" : "=l"(r) : "r"(__float_as_uint(lo)), "r"(__float_as_uint(hi)));
    return r;
}
__device__ __forceinline__ unsigned long long fma_f32x2(unsigned long long a,
                                                        unsigned long long b,
                                                        unsigned long long c) {
    unsigned long long d;
    asm("fma.rn.f32x2 %0, %1, %2, %3;" : "=l"(d) : "l"(a), "l"(b), "l"(c));
    return d;
}
__device__ __forceinline__ float hsum_f32x2(unsigned long long v) {
    unsigned a, b;
    asm("mov.b64 {%0, %1}, %2;" : "=r"(a), "=r"(b) : "l"(v));
    return __uint_as_float(a) + __uint_as_float(b);
}

// ---------------- named-barrier producer/consumer sync ----------------
#define BAR_FULL(s)  (1 + (s))     // ids 1,2
#define BAR_EMPTY(s) (3 + (s))     // ids 3,4
__device__ __forceinline__ void nbar_sync(int id) {
    asm volatile("bar.sync %0, %1;" :: "r"(id), "r"(TPB) : "memory");
}
__device__ __forceinline__ void nbar_arrive(int id) {
    asm volatile("bar.arrive %0, %1;" :: "r"(id), "r"(TPB) : "memory");
}

// ---- one hash level for TWO points: all 8 a-loads issued before any consume ----
__device__ __forceinline__ void gather2(int l, float rs,
                                        float xA, float yA, float zA,
                                        float xB, float yB, float zB,
                                        const float* __restrict__ tables,
                                        float2 (*st)[TILE_P], int tid)
{
    // indices, point A
    const float pxA = xA * rs, pyA = yA * rs, pzA = zA * rs;
    const float fxA = floorf(pxA), fyA = floorf(pyA), fzA = floorf(pzA);
    const float txA = pxA - fxA, tyA = pyA - fyA, tzA = pzA - fzA;
    const unsigned ixA = (unsigned)fxA, iyA = (unsigned)fyA, izA = (unsigned)fzA;
    const unsigned hyA0 = iyA * PRIME_Y, hyA1 = hyA0 + PRIME_Y;
    const unsigned hzA0 = izA * PRIME_Z, hzA1 = hzA0 + PRIME_Z;
    const unsigned xmA  = ixA ^ (ixA + 1u);
    const bool     oddA = (ixA & 1u) != 0u;
    const unsigned qA00 = (ixA ^ hyA0 ^ hzA0) & TMASK;
    const unsigned qA01 = (ixA ^ hyA0 ^ hzA1) & TMASK;
    const unsigned qA10 = (ixA ^ hyA1 ^ hzA0) & TMASK;
    const unsigned qA11 = (ixA ^ hyA1 ^ hzA1) & TMASK;

    // indices, point B
    const float pxB = xB * rs, pyB = yB * rs, pzB = zB * rs;
    const float fxB = floorf(pxB), fyB = floorf(pyB), fzB = floorf(pzB);
    const float txB = pxB - fxB, tyB = pyB - fyB, tzB = pzB - fzB;
    const unsigned ixB = (unsigned)fxB, iyB = (unsigned)fyB, izB = (unsigned)fzB;
    const unsigned hyB0 = iyB * PRIME_Y, hyB1 = hyB0 + PRIME_Y;
    const unsigned hzB0 = izB * PRIME_Z, hzB1 = hzB0 + PRIME_Z;
    const unsigned xmB  = ixB ^ (ixB + 1u);
    const bool     oddB = (ixB & 1u) != 0u;
    const unsigned qB00 = (ixB ^ hyB0 ^ hzB0) & TMASK;
    const unsigned qB01 = (ixB ^ hyB0 ^ hzB1) & TMASK;
    const unsigned qB10 = (ixB ^ hyB1 ^ hzB0) & TMASK;
    const unsigned qB11 = (ixB ^ hyB1 ^ hzB1) & TMASK;

    const float4* __restrict__ t4 = (const float4*)tables + (size_t)l * (TBL / 2);
    const float2* __restrict__ t2 = (const float2*)tables + (size_t)l * TBL;

    // 8 always-on loads issued back-to-back (max MLP)
    const float4 aA00 = __ldg(t4 + (qA00 >> 1));
    const float4 aA01 = __ldg(t4 + (qA01 >> 1));
    const float4 aA10 = __ldg(t4 + (qA10 >> 1));
    const float4 aA11 = __ldg(t4 + (qA11 >> 1));
    const float4 aB00 = __ldg(t4 + (qB00 >> 1));
    const float4 aB01 = __ldg(t4 + (qB01 >> 1));
    const float4 aB10 = __ldg(t4 + (qB10 >> 1));
    const float4 aB11 = __ldg(t4 + (qB11 >> 1));

    // predicated odd-x loads (exact x1 entries)
    float2 dA00, dA01, dA10, dA11, dB00, dB01, dB10, dB11;
    if (oddA) {
        dA00 = __ldg(t2 + ((qA00 ^ xmA) & TMASK));
        dA01 = __ldg(t2 + ((qA01 ^ xmA) & TMASK));
        dA10 = __ldg(t2 + ((qA10 ^ xmA) & TMASK));
        dA11 = __ldg(t2 + ((qA11 ^ xmA) & TMASK));
    }
    if (oddB) {
        dB00 = __ldg(t2 + ((qB00 ^ xmB) & TMASK));
        dB01 = __ldg(t2 + ((qB01 ^ xmB) & TMASK));
        dB10 = __ldg(t2 + ((qB10 ^ xmB) & TMASK));
        dB11 = __ldg(t2 + ((qB11 ^ xmB) & TMASK));
    }

    // ---- consume point A ----
    {
        const float f000x = (qA00 & 1) ? aA00.z : aA00.x, f000y = (qA00 & 1) ? aA00.w : aA00.y;
        const float f001x = (qA01 & 1) ? aA01.z : aA01.x, f001y = (qA01 & 1) ? aA01.w : aA01.y;
        const float f010x = (qA10 & 1) ? aA10.z : aA10.x, f010y = (qA10 & 1) ? aA10.w : aA10.y;
        const float f011x = (qA11 & 1) ? aA11.z : aA11.x, f011y = (qA11 & 1) ? aA11.w : aA11.y;
        float f100x, f100y, f101x, f101y, f110x, f110y, f111x, f111y;
        if (oddA) {
            f100x = dA00.x; f100y = dA00.y;  f101x = dA01.x; f101y = dA01.y;
            f110x = dA10.x; f110y = dA10.y;  f111x = dA11.x; f111y = dA11.y;
        } else {
            f100x = (qA00 & 1) ? aA00.x : aA00.z;  f100y = (qA00 & 1) ? aA00.y : aA00.w;
            f101x = (qA01 & 1) ? aA01.x : aA01.z;  f101y = (qA01 & 1) ? aA01.y : aA01.w;
            f110x = (qA10 & 1) ? aA10.x : aA10.z;  f110y = (qA10 & 1) ? aA10.y : aA10.w;
            f111x = (qA11 & 1) ? aA11.x : aA11.z;  f111y = (qA11 & 1) ? aA11.y : aA11.w;
        }
        const float ux = 1.f - txA, uy = 1.f - tyA, uz = 1.f - tzA;
        const float a0 = ux * uy, a1 = ux * tyA, a2 = txA * uy, a3 = txA * tyA;
        const float w000 = a0 * uz, w001 = a0 * tzA;
        const float w010 = a1 * uz, w011 = a1 * tzA;
        const float w100 = a2 * uz, w101 = a2 * tzA;
        const float w110 = a3 * uz, w111 = a3 * tzA;
        float e0, e1;
        e0 = w000 * f000x;           e1 = w000 * f000y;
        e0 = fmaf(w001, f001x, e0);  e1 = fmaf(w001, f001y, e1);
        e0 = fmaf(w010, f010x, e0);  e1 = fmaf(w010, f010y, e1);
        e0 = fmaf(w011, f011x, e0);  e1 = fmaf(w011, f011y, e1);
        e0 = fmaf(w100, f100x, e0);  e1 = fmaf(w100, f100y, e1);
        e0 = fmaf(w101, f101x, e0);  e1 = fmaf(w101, f101y, e1);
        e0 = fmaf(w110, f110x, e0);  e1 = fmaf(w110, f110y, e1);
        e0 = fmaf(w111, f111x, e0);  e1 = fmaf(w111, f111y, e1);
        st[l][tid] = make_float2(e0, e1);
    }
    // ---- consume point B ----
    {
        const float f000x = (qB00 & 1) ? aB00.z : aB00.x, f000y = (qB00 & 1) ? aB00.w : aB00.y;
        const float f001x = (qB01 & 1) ? aB01.z : aB01.x, f001y = (qB01 & 1) ? aB01.w : aB01.y;
        const float f010x = (qB10 & 1) ? aB10.z : aB10.x, f010y = (qB10 & 1) ? aB10.w : aB10.y;
        const float f011x = (qB11 & 1) ? aB11.z : aB11.x, f011y = (qB11 & 1) ? aB11.w : aB11.y;
        float f100x, f100y, f101x, f101y, f110x, f110y, f111x, f111y;
        if (oddB) {
            f100x = dB00.x; f100y = dB00.y;  f101x = dB01.x; f101y = dB01.y;
            f110x = dB10.x; f110y = dB10.y;  f111x = dB11.x; f111y = dB11.y;
        } else {
            f100x = (qB00 & 1) ? aB00.x : aB00.z;  f100y = (qB00 & 1) ? aB00.y : aB00.w;
            f101x = (qB01 & 1) ? aB01.x : aB01.z;  f101y = (qB01 & 1) ? aB01.y : aB01.w;
            f110x = (qB10 & 1) ? aB10.x : aB10.z;  f110y = (qB10 & 1) ? aB10.y : aB10.w;
            f111x = (qB11 & 1) ? aB11.x : aB11.z;  f111y = (qB11 & 1) ? aB11.y : aB11.w;
        }
        const float ux = 1.f - txB, uy = 1.f - tyB, uz = 1.f - tzB;
        const float a0 = ux * uy, a1 = ux * tyB, a2 = txB * uy, a3 = txB * tyB;
        const float w000 = a0 * uz, w001 = a0 * tzB;
        const float w010 = a1 * uz, w011 = a1 * tzB;
        const float w100 = a2 * uz, w101 = a2 * tzB;
        const float w110 = a3 * uz, w111 = a3 * tzB;
        float e0, e1;
        e0 = w000 * f000x;           e1 = w000 * f000y;
        e0 = fmaf(w001, f001x, e0);  e1 = fmaf(w001, f001y, e1);
        e0 = fmaf(w010, f010x, e0);  e1 = fmaf(w010, f010y, e1);
        e0 = fmaf(w011, f011x, e0);  e1 = fmaf(w011, f011y, e1);
        e0 = fmaf(w100, f100x, e0);  e1 = fmaf(w100, f100y, e1);
        e0 = fmaf(w101, f101x, e0);  e1 = fmaf(w101, f101y, e1);
        e0 = fmaf(w110, f110x, e0);  e1 = fmaf(w110, f110y, e1);
        e0 = fmaf(w111, f111x, e0);  e1 = fmaf(w111, f111y, e1);
        st[l][tid + 128] = make_float2(e0, e1);
    }
}

// ---- head: 4 points x 2 columns (proven R9/R11 code) ----
__device__ __forceinline__ void head4(const float2 (*sEmb)[TILE_P], int pbase, int pg,
                                      int c0, int c1,
                                      const unsigned long long* w0,
                                      const unsigned long long* w1,
                                      unsigned long long b0, unsigned long long b1,
                                      float* __restrict__ out, int N)
{
    unsigned long long acc0[4] = {b0, b0, b0, b0};
    unsigned long long acc1[4] = {b1, b1, b1, b1};
#pragma unroll
    for (int l = 0; l < NLVL; ++l) {
        const ulonglong2 eA = *(const ulonglong2*)&sEmb[l][pg];
        const ulonglong2 eB = *(const ulonglong2*)&sEmb[l][pg + 2];
        acc0[0] = fma_f32x2(eA.x, w0[l], acc0[0]);
        acc1[0] = fma_f32x2(eA.x, w1[l], acc1[0]);
        acc0[1] = fma_f32x2(eA.y, w0[l], acc0[1]);
        acc1[1] = fma_f32x2(eA.y, w1[l], acc1[1]);
        acc0[2] = fma_f32x2(eB.x, w0[l], acc0[2]);
        acc1[2] = fma_f32x2(eB.x, w1[l], acc1[2]);
        acc0[3] = fma_f32x2(eB.y, w0[l], acc0[3]);
        acc1[3] = fma_f32x2(eB.y, w1[l], acc1[3]);
    }
#pragma unroll
    for (int i = 0; i < 4; ++i) {
        const int prow = pbase + pg + i;
        if (prow < N) {
            const size_t row = (size_t)prow * DOUT;
            __stcs(&out[row + c0], hsum_f32x2(acc0[i]));
            __stcs(&out[row + c1], hsum_f32x2(acc1[i]));
        }
    }
}

__global__ __launch_bounds__(TPB, 2)
void hashsdf_kernel(const float* __restrict__ inputs,
                    const float* __restrict__ tables,
                    const float* __restrict__ W,
                    const float* __restrict__ bias,
                    float* __restrict__ out,
                    int N, int ntiles, Params prm)
{
    __shared__ __align__(16) float2 sEmb[STAGES][NLVL][TILE_P];   // 48 KB exactly

    const int tid = threadIdx.x;

    if (tid < 128) {
        // ================= PRODUCER: hash-grid encode, 2 pts/thread =================
        int j = 0;
        for (int t = blockIdx.x; t < ntiles; t += gridDim.x, ++j) {
            const int s = j & 1;
            if (j >= STAGES) nbar_sync(BAR_EMPTY(s));

            const int pbase = t * TILE_P;
            const int pA = pbase + tid, pB = pA + 128;
            float xA = 0.f, yA = 0.f, zA = 0.f, xB = 0.f, yB = 0.f, zB = 0.f;
            if (pA < N) { xA = inputs[3 * pA]; yA = inputs[3 * pA + 1]; zA = inputs[3 * pA + 2]; }
            if (pB < N) { xB = inputs[3 * pB]; yB = inputs[3 * pB + 1]; zB = inputs[3 * pB + 2]; }

#pragma unroll
            for (int l = 0; l < NLVL; ++l)
                gather2(l, (float)prm.res[l], xA, yA, zA, xB, yB, zB,
                        tables, sEmb[s], tid);

            nbar_arrive(BAR_FULL(s));
        }
    } else {
        // ================= CONSUMER: [24 x 257] linear head =================
        const int ct   = tid - 128;
        const int cw   = ct >> 5;
        const int lane = ct & 31;
        const int c0   = cw * 64 + lane;
        const int c1   = c0 + 32;

        unsigned long long w0[NLVL], w1[NLVL];
        float w256[EMBD];
#pragma unroll
        for (int l = 0; l < NLVL; ++l) {
            w0[l] = pack2_f32(__ldg(&W[(2 * l) * DOUT + c0]), __ldg(&W[(2 * l + 1) * DOUT + c0]));
            w1[l] = pack2_f32(__ldg(&W[(2 * l) * DOUT + c1]), __ldg(&W[(2 * l + 1) * DOUT + c1]));
            w256[2 * l + 0] = __ldg(&W[(2 * l) * DOUT + 256]);
            w256[2 * l + 1] = __ldg(&W[(2 * l + 1) * DOUT + 256]);
        }
        const unsigned long long b0 = pack2_f32(__ldg(&bias[c0]), 0.f);
        const unsigned long long b1 = pack2_f32(__ldg(&bias[c1]), 0.f);
        const float b256 = __ldg(&bias[256]);

        int j = 0;
        for (int t = blockIdx.x; t < ntiles; t += gridDim.x, ++j) {
            const int s = j & 1;
            nbar_sync(BAR_FULL(s));

            const int pbase = t * TILE_P;
            for (int pg = 0; pg < TILE_P; pg += 4)
                head4(sEmb[s], pbase, pg, c0, c1, w0, w1, b0, b1, out, N);

            // col-256 epilogue: consumer thread handles points ct and ct+128
#pragma unroll
            for (int half = 0; half < 2; ++half) {
                const int pt = ct + half * 128;
                float acc = b256;
#pragma unroll
                for (int l = 0; l < NLVL; ++l) {
                    const float2 e = sEmb[s][l][pt];
                    acc = fmaf(e.x, w256[2 * l + 0], acc);
                    acc = fmaf(e.y, w256[2 * l + 1], acc);
                }
                const int prow = pbase + pt;
                if (prow < N) __stcs(&out[(size_t)prow * DOUT + 256], acc);
            }

            nbar_arrive(BAR_EMPTY(s));
        }
    }
}

extern "C" void kernel_launch(void* const* d_in, const int* in_sizes, int n_in,
                              void* d_out, int out_size) {
    const float* inputs = (const float*)d_in[0];
    const float* tables = (const float*)d_in[1];
    const float* W      = (const float*)d_in[2];
    const float* bias   = (const float*)d_in[3];
    float* out          = (float*)d_out;

    const int N = in_sizes[0] / 3;

    // Replicate numpy's RES computation bit-exactly (RES[11] is analytically 2048;
    // floor outcome depends on libm rounding — do NOT hardcode).
    Params prm;
    const double growth = exp((log(2048.0) - log(16.0)) / 11.0);
    for (int l = 0; l < NLVL; ++l)
        prm.res[l] = (int)floor(16.0 * pow(growth, (double)l));

    int nsm = 148;
    cudaDeviceGetAttribute(&nsm, cudaDevAttrMultiProcessorCount, 0);

    const int ntiles = (N + TILE_P - 1) / TILE_P;
    int grid = 2 * nsm;
    if (grid > ntiles) grid = ntiles;

    hashsdf_kernel<<<grid, TPB>>>(inputs, tables, W, bias, out, N, ntiles, prm);
}

// round 16
// speedup vs baseline: 1.0250x; 1.0250x over previous
#include <cuda_runtime.h>
#include <math.h>
#include <stdint.h>

// ---------------- problem constants ----------------
#define NLVL   12
#define TBL    (1u << 19)
#define TMASK  (TBL - 1u)
#define EMBD   24
#define DOUT   257
#define TPB    256
#define TILE_P 256

#define PRIME_Y 2654435761u
#define PRIME_Z 805459861u

struct Params { int res[NLVL]; };

// ---------------- f32x2 packed helpers (sm_103a) ----------------
__device__ __forceinline__ unsigned long long pack2_f32(float lo, float hi) {
    unsigned long long r;
    asm("mov.b64 %0, {%1, %2};" : "=l"(r) : "r"(__float_as_uint(lo)), "r"(__float_as_uint(hi)));
    return r;
}
__device__ __forceinline__ unsigned long long fma_f32x2(unsigned long long a,
                                                        unsigned long long b,
                                                        unsigned long long c) {
    unsigned long long d;
    asm("fma.rn.f32x2 %0, %1, %2, %3;" : "=l"(d) : "l"(a), "l"(b), "l"(c));
    return d;
}
__device__ __forceinline__ float hsum_f32x2(unsigned long long v) {
    unsigned a, b;
    asm("mov.b64 {%0, %1}, %2;" : "=r"(a), "=r"(b) : "l"(v));
    return __uint_as_float(a) + __uint_as_float(b);
}
// named barrier over 128 threads (ids 1,2; warps never straddle halves)
__device__ __forceinline__ void half_bar(int id) {
    asm volatile("bar.sync %0, 128;" :: "r"(id) : "memory");
}

// ---------------- split gather: issue (loads in flight) / consume ----------------
struct Lv {
    float4 a00, a01, a10, a11;   // x0-corner float4 pairs (always loaded)
    float2 d00, d01, d10, d11;   // exact x1 entries (odd ix only)
    unsigned q00, q01, q10, q11;
    float tx, ty, tz;
    unsigned odd;
};

__device__ __forceinline__ Lv issue_level(int l, float rs, float x, float y, float z,
                                          const float* __restrict__ tables)
{
    Lv v;
    const float px = x * rs, py = y * rs, pz = z * rs;
    const float fx = floorf(px), fy = floorf(py), fz = floorf(pz);
    v.tx = px - fx; v.ty = py - fy; v.tz = pz - fz;
    const unsigned ix = (unsigned)fx, iy = (unsigned)fy, iz = (unsigned)fz;
    const unsigned hy0 = iy * PRIME_Y, hy1 = hy0 + PRIME_Y;
    const unsigned hz0 = iz * PRIME_Z, hz1 = hz0 + PRIME_Z;
    const unsigned xm  = ix ^ (ix + 1u);
    v.odd = ix & 1u;
    v.q00 = (ix ^ hy0 ^ hz0) & TMASK;
    v.q01 = (ix ^ hy0 ^ hz1) & TMASK;
    v.q10 = (ix ^ hy1 ^ hz0) & TMASK;
    v.q11 = (ix ^ hy1 ^ hz1) & TMASK;

    const float4* __restrict__ t4 = (const float4*)tables + (size_t)l * (TBL / 2);
    const float2* __restrict__ t2 = (const float2*)tables + (size_t)l * TBL;

    v.a00 = __ldg(t4 + (v.q00 >> 1));
    v.a01 = __ldg(t4 + (v.q01 >> 1));
    v.a10 = __ldg(t4 + (v.q10 >> 1));
    v.a11 = __ldg(t4 + (v.q11 >> 1));
    if (v.odd) {
        v.d00 = __ldg(t2 + ((v.q00 ^ xm) & TMASK));
        v.d01 = __ldg(t2 + ((v.q01 ^ xm) & TMASK));
        v.d10 = __ldg(t2 + ((v.q10 ^ xm) & TMASK));
        v.d11 = __ldg(t2 + ((v.q11 ^ xm) & TMASK));
    }
    return v;
}

__device__ __forceinline__ void consume_level(const Lv& v, int l,
                                              float2 (*st)[TILE_P], int tid)
{
    const float f000x = (v.q00 & 1) ? v.a00.z : v.a00.x, f000y = (v.q00 & 1) ? v.a00.w : v.a00.y;
    const float f001x = (v.q01 & 1) ? v.a01.z : v.a01.x, f001y = (v.q01 & 1) ? v.a01.w : v.a01.y;
    const float f010x = (v.q10 & 1) ? v.a10.z : v.a10.x, f010y = (v.q10 & 1) ? v.a10.w : v.a10.y;
    const float f011x = (v.q11 & 1) ? v.a11.z : v.a11.x, f011y = (v.q11 & 1) ? v.a11.w : v.a11.y;

    float f100x, f100y, f101x, f101y, f110x, f110y, f111x, f111y;
    if (v.odd) {
        f100x = v.d00.x; f100y = v.d00.y;  f101x = v.d01.x; f101y = v.d01.y;
        f110x = v.d10.x; f110y = v.d10.y;  f111x = v.d11.x; f111y = v.d11.y;
    } else {
        f100x = (v.q00 & 1) ? v.a00.x : v.a00.z;  f100y = (v.q00 & 1) ? v.a00.y : v.a00.w;
        f101x = (v.q01 & 1) ? v.a01.x : v.a01.z;  f101y = (v.q01 & 1) ? v.a01.y : v.a01.w;
        f110x = (v.q10 & 1) ? v.a10.x : v.a10.z;  f110y = (v.q10 & 1) ? v.a10.y : v.a10.w;
        f111x = (v.q11 & 1) ? v.a11.x : v.a11.z;  f111y = (v.q11 & 1) ? v.a11.y : v.a11.w;
    }

    const float ux = 1.f - v.tx, uy = 1.f - v.ty, uz = 1.f - v.tz;
    const float a0 = ux * uy, a1 = ux * v.ty, a2 = v.tx * uy, a3 = v.tx * v.ty;
    const float w000 = a0 * uz, w001 = a0 * v.tz;
    const float w010 = a1 * uz, w011 = a1 * v.tz;
    const float w100 = a2 * uz, w101 = a2 * v.tz;
    const float w110 = a3 * uz, w111 = a3 * v.tz;

    float e0, e1;
    e0 = w000 * f000x;           e1 = w000 * f000y;
    e0 = fmaf(w001, f001x, e0);  e1 = fmaf(w001, f001y, e1);
    e0 = fmaf(w010, f010x, e0);  e1 = fmaf(w010, f010y, e1);
    e0 = fmaf(w011, f011x, e0);  e1 = fmaf(w011, f011y, e1);
    e0 = fmaf(w100, f100x, e0);  e1 = fmaf(w100, f100y, e1);
    e0 = fmaf(w101, f101x, e0);  e1 = fmaf(w101, f101y, e1);
    e0 = fmaf(w110, f110x, e0);  e1 = fmaf(w110, f110y, e1);
    e0 = fmaf(w111, f111x, e0);  e1 = fmaf(w111, f111y, e1);

    st[l][tid] = make_float2(e0, e1);
}

// fused issue+consume (dense stream for the standalone first tile)
__device__ __forceinline__ void gather_level(int l, float rs,
                                             float x, float y, float z,
                                             const float* __restrict__ tables,
                                             float2 (*st)[TILE_P], int tid)
{
    const Lv v = issue_level(l, rs, x, y, z, tables);
    consume_level(v, l, st, tid);
}

// ---- head: 4 points x 2 columns from a staged tile (proven R9/R11 code) ----
__device__ __forceinline__ void head4(const float2 (*sEmb)[TILE_P], int pbase, int pg,
                                      int c0, int c1,
                                      const unsigned long long* w0,
                                      const unsigned long long* w1,
                                      unsigned long long b0, unsigned long long b1,
                                      float* __restrict__ out, int N)
{
    unsigned long long acc0[4] = {b0, b0, b0, b0};
    unsigned long long acc1[4] = {b1, b1, b1, b1};
#pragma unroll
    for (int l = 0; l < NLVL; ++l) {
        const ulonglong2 eA = *(const ulonglong2*)&sEmb[l][pg];
        const ulonglong2 eB = *(const ulonglong2*)&sEmb[l][pg + 2];
        acc0[0] = fma_f32x2(eA.x, w0[l], acc0[0]);
        acc1[0] = fma_f32x2(eA.x, w1[l], acc1[0]);
        acc0[1] = fma_f32x2(eA.y, w0[l], acc0[1]);
        acc1[1] = fma_f32x2(eA.y, w1[l], acc1[1]);
        acc0[2] = fma_f32x2(eB.x, w0[l], acc0[2]);
        acc1[2] = fma_f32x2(eB.x, w1[l], acc1[2]);
        acc0[3] = fma_f32x2(eB.y, w0[l], acc0[3]);
        acc1[3] = fma_f32x2(eB.y, w1[l], acc1[3]);
    }
#pragma unroll
    for (int i = 0; i < 4; ++i) {
        const int prow = pbase + pg + i;
        if (prow < N) {
            const size_t row = (size_t)prow * DOUT;
            __stcs(&out[row + c0], hsum_f32x2(acc0[i]));
            __stcs(&out[row + c1], hsum_f32x2(acc1[i]));
        }
    }
}

__device__ __forceinline__ void epilogue256(const float2 (*sEmb)[TILE_P], int tid,
                                            int pbase,
                                            const float* __restrict__ W,
                                            const float* __restrict__ bias,
                                            float* __restrict__ out, int N)
{
    float acc = __ldg(&bias[256]);
#pragma unroll
    for (int l = 0; l < NLVL; ++l) {
        const float2 e = sEmb[l][tid];
        acc = fmaf(e.x, __ldg(&W[(2 * l) * DOUT + 256]), acc);
        acc = fmaf(e.y, __ldg(&W[(2 * l + 1) * DOUT + 256]), acc);
    }
    const int prow = pbase + tid;
    if (prow < N) __stcs(&out[(size_t)prow * DOUT + 256], acc);
}

__global__ __launch_bounds__(TPB, 2)
void hashsdf_kernel(const float* __restrict__ inputs,
                    const float* __restrict__ tables,
                    const float* __restrict__ W,
                    const float* __restrict__ bias,
                    float* __restrict__ out,
                    int N, int ntiles, Params prm)
{
    __shared__ __align__(16) float2 sA[NLVL][TILE_P];
    __shared__ __align__(16) float2 sB[NLVL][TILE_P];

    const int tid    = threadIdx.x;
    const int halfid = 1 + (tid >> 7);

    const int t0 = 2 * blockIdx.x;
    const int t1 = (t0 + 1 < ntiles) ? t0 + 1 : t0;  // degenerate duplicate (benign)
    const int pbase0 = t0 * TILE_P;
    const int pbase1 = t1 * TILE_P;

    // ---------------- standalone gather of tile t0 -> sA (dense stream) ----------------
    {
        const int p = pbase0 + tid;
        float x = 0.f, y = 0.f, z = 0.f;
        if (p < N) { x = inputs[3 * p + 0]; y = inputs[3 * p + 1]; z = inputs[3 * p + 2]; }
#pragma unroll
        for (int l = 0; l < NLVL; ++l)
            gather_level(l, (float)prm.res[l], x, y, z, tables, sA, tid);
    }
    half_bar(halfid);

    // coords for t1
    float x1 = 0.f, y1 = 0.f, z1 = 0.f;
    {
        const int p = pbase1 + tid;
        if (p < N) { x1 = inputs[3 * p + 0]; y1 = inputs[3 * p + 1]; z1 = inputs[3 * p + 2]; }
    }

    // head setup (shared by both tiles)
    const int wid  = tid >> 5;
    const int lane = tid & 31;
    const int g    = wid & 3;
    const int h    = wid >> 2;
    const int c0   = g * 64 + lane;
    const int c1   = c0 + 32;

    unsigned long long w0[NLVL], w1[NLVL];
#pragma unroll
    for (int l = 0; l < NLVL; ++l) {
        w0[l] = pack2_f32(__ldg(&W[(2 * l) * DOUT + c0]), __ldg(&W[(2 * l + 1) * DOUT + c0]));
        w1[l] = pack2_f32(__ldg(&W[(2 * l) * DOUT + c1]), __ldg(&W[(2 * l + 1) * DOUT + c1]));
    }
    const unsigned long long b0 = pack2_f32(__ldg(&bias[c0]), 0.f);
    const unsigned long long b1 = pack2_f32(__ldg(&bias[c1]), 0.f);

    // ------- merged: head(t0) with t1 gathers software-pipelined underneath -------
    // Loads for level u are issued, a full head4 chunk (~300 cyc) runs while they
    // are in flight, THEN they are consumed and level u+1 issues. The warp never
    // blocks on a gather while head work remains.
    {
        int pg = h * 128;
        Lv cur = issue_level(0, (float)prm.res[0], x1, y1, z1, tables);
        for (int u = 0; u < NLVL; ++u) {
            head4(sA, pbase0, pg, c0, c1, w0, w1, b0, b1, out, N);
            pg += 4;
            consume_level(cur, u, sB, tid);
            if (u + 1 < NLVL)
                cur = issue_level(u + 1, (float)prm.res[u + 1], x1, y1, z1, tables);
        }
        // remaining 20 head chunks of tile t0
        const int pg_end = h * 128 + 128;
        for (; pg < pg_end; pg += 4)
            head4(sA, pbase0, pg, c0, c1, w0, w1, b0, b1, out, N);
    }
    epilogue256(sA, tid, pbase0, W, bias, out, N);

    half_bar(halfid);

    // ---------------- head of tile t1 from sB ----------------
    {
        const int pg_end = h * 128 + 128;
        for (int pg = h * 128; pg < pg_end; pg += 4)
            head4(sB, pbase1, pg, c0, c1, w0, w1, b0, b1, out, N);
    }
    epilogue256(sB, tid, pbase1, W, bias, out, N);
}

extern "C" void kernel_launch(void* const* d_in, const int* in_sizes, int n_in,
                              void* d_out, int out_size) {
    const float* inputs = (const float*)d_in[0];
    const float* tables = (const float*)d_in[1];
    const float* W      = (const float*)d_in[2];
    const float* bias   = (const float*)d_in[3];
    float* out          = (float*)d_out;

    const int N = in_sizes[0] / 3;

    // Replicate numpy's RES computation bit-exactly (RES[11] is analytically 2048;
    // floor outcome depends on libm rounding — do NOT hardcode).
    Params prm;
    const double growth = exp((log(2048.0) - log(16.0)) / 11.0);
    for (int l = 0; l < NLVL; ++l)
        prm.res[l] = (int)floor(16.0 * pow(growth, (double)l));

    const int ntiles = (N + TILE_P - 1) / TILE_P;
    const int grid   = (ntiles + 1) / 2;      // 2 tiles per block

    hashsdf_kernel<<<grid, TPB>>>(inputs, tables, W, bias, out, N, ntiles, prm);
}